// round 6
// baseline (speedup 1.0000x reference)
#include <cuda_runtime.h>

#define NFFT 1024
#define TPB  64
// float2-word skew: conflict-free for ALL four access patterns used below
#define SK(a) ((a) + ((a) >> 4))

#define CMUL(r, i, cr, ci) { float _t = (r)*(cr) - (i)*(ci); (i) = (r)*(ci) + (i)*(cr); (r) = _t; }

// Inverse 4-pt DFT (twiddle sign +i), outputs in natural order.
__device__ __forceinline__ void idft4(
    float ar, float ai, float br, float bi,
    float cr, float ci, float dr, float di,
    float& o0r, float& o0i, float& o1r, float& o1i,
    float& o2r, float& o2i, float& o3r, float& o3i)
{
    float t0r = ar + cr, t0i = ai + ci;
    float t1r = ar - cr, t1i = ai - ci;
    float t2r = br + dr, t2i = bi + di;
    float t3r = br - dr, t3i = bi - di;
    o0r = t0r + t2r;  o0i = t0i + t2i;
    o2r = t0r - t2r;  o2i = t0i - t2i;
    o1r = t1r - t3i;  o1i = t1i + t3r;   // + i*t3
    o3r = t1r + t3i;  o3i = t1i - t3r;   // - i*t3
}

// Inverse 16-pt DFT (sign +i), natural-order in/out, via 4x4 decomposition.
__device__ __forceinline__ void idft16(const float* xr, const float* xi,
                                       float* Xr, float* Xi)
{
    const float C1 = 0.9238795325112867f;   // cos(pi/8)
    const float S1 = 0.3826834323650898f;   // sin(pi/8)
    const float C2 = 0.7071067811865476f;

    float yr[16], yi[16];
    #pragma unroll
    for (int n0 = 0; n0 < 4; n0++) {
        idft4(xr[n0], xi[n0], xr[n0+4], xi[n0+4],
              xr[n0+8], xi[n0+8], xr[n0+12], xi[n0+12],
              yr[n0], yi[n0], yr[n0+4], yi[n0+4],
              yr[n0+8], yi[n0+8], yr[n0+12], yi[n0+12]);
    }
    CMUL(yr[5],  yi[5],   C1,  S1);
    CMUL(yr[9],  yi[9],   C2,  C2);
    CMUL(yr[13], yi[13],  S1,  C1);
    CMUL(yr[6],  yi[6],   C2,  C2);
    { float t = yr[10]; yr[10] = -yi[10]; yi[10] = t; }
    CMUL(yr[14], yi[14], -C2,  C2);
    CMUL(yr[7],  yi[7],   S1,  C1);
    CMUL(yr[11], yi[11], -C2,  C2);
    CMUL(yr[15], yi[15], -C1, -S1);
    #pragma unroll
    for (int m = 0; m < 4; m++) {
        idft4(yr[4*m+0], yi[4*m+0], yr[4*m+1], yi[4*m+1],
              yr[4*m+2], yi[4*m+2], yr[4*m+3], yi[4*m+3],
              Xr[m],    Xi[m],    Xr[m+4],  Xi[m+4],
              Xr[m+8],  Xi[m+8],  Xr[m+12], Xi[m+12]);
    }
}

__global__ __launch_bounds__(TPB, 21)
void ifft1024_v6(const float* __restrict__ xre,
                 const float* __restrict__ xim,
                 float* __restrict__ ore,
                 float* __restrict__ oim)
{
    __shared__ float2 s[1088];   // 1024 + skew padding

    const int t = threadIdx.x;   // 0..63
    const size_t base = (size_t)blockIdx.x * NFFT;
    const float scale = 1.0f / (float)NFFT;
    const float TWO_PI = 6.283185307179586f;

    float xr[16], xi[16], Xr[16], Xi[16];

    // ============ stage 0: radix-16, L=1 (global read, coalesced) ============
    #pragma unroll
    for (int c = 0; c < 16; c++) {
        xr[c] = __ldcs(xre + base + t + 64 * c) * scale;
        xi[c] = __ldcs(xim + base + t + 64 * c) * scale;
    }
    idft16(xr, xi, Xr, Xi);
    #pragma unroll
    for (int c = 0; c < 16; c++)
        s[SK(16 * t + c)] = make_float2(Xr[c], Xi[c]);
    __syncthreads();

    // ============ stage 1: radix-16, L=16 (in-place: read-all, sync, write) ============
    #pragma unroll
    for (int c = 0; c < 16; c++) {
        float2 v = s[SK(t + 64 * c)];
        xr[c] = v.x;  xi[c] = v.y;
    }
    __syncthreads();
    {   // twiddle: x[c] *= W256^{b*c}, b = t mod 16
        const int b = t & 15;
        float wr, wi;
        __sincosf(TWO_PI * (float)b * (1.0f / 256.0f), &wi, &wr);
        float cwr = wr, cwi = wi;
        #pragma unroll
        for (int c = 1; c < 16; c++) {
            CMUL(xr[c], xi[c], cwr, cwi);
            if (c < 15) { float nr = cwr*wr - cwi*wi; cwi = cwr*wi + cwi*wr; cwr = nr; }
        }
    }
    idft16(xr, xi, Xr, Xi);
    {
        const int wb = (t & 15) + ((t >> 4) << 8);   // b + 256*(t/16)
        #pragma unroll
        for (int c = 0; c < 16; c++)
            s[SK(wb + 16 * c)] = make_float2(Xr[c], Xi[c]);
    }
    __syncthreads();

    // ============ stage 2: radix-4, L=256, j = 4t+d, natural-order global store ============
    {
        float outR[4][4], outI[4][4];   // [k][d]
        float wr, wi;
        __sincosf(TWO_PI * (float)(4 * t) * (1.0f / 1024.0f), &wi, &wr);
        const float dc = 0.9999811752826011f;    // cos(2*pi/1024)
        const float ds = 0.006135884649154475f;  // sin(2*pi/1024)

        #pragma unroll
        for (int d = 0; d < 4; d++) {
            const int j = 4 * t + d;
            float ar[4], ai[4];
            #pragma unroll
            for (int k = 0; k < 4; k++) {
                float2 v = s[SK(j + 256 * k)];
                ar[k] = v.x;  ai[k] = v.y;
            }
            float w2r = wr*wr - wi*wi, w2i = 2.0f*wr*wi;
            float w3r = w2r*wr - w2i*wi, w3i = w2r*wi + w2i*wr;
            CMUL(ar[1], ai[1], wr,  wi);
            CMUL(ar[2], ai[2], w2r, w2i);
            CMUL(ar[3], ai[3], w3r, w3i);
            idft4(ar[0], ai[0], ar[1], ai[1], ar[2], ai[2], ar[3], ai[3],
                  outR[0][d], outI[0][d], outR[1][d], outI[1][d],
                  outR[2][d], outI[2][d], outR[3][d], outI[3][d]);
            if (d < 3) { float nr = wr*dc - wi*ds; wi = wr*ds + wi*dc; wr = nr; }
        }
        #pragma unroll
        for (int k = 0; k < 4; k++) {
            const size_t o = base + (size_t)(4 * t + 256 * k);
            float4 vr = make_float4(outR[k][0], outR[k][1], outR[k][2], outR[k][3]);
            float4 vi = make_float4(outI[k][0], outI[k][1], outI[k][2], outI[k][3]);
            __stcs((float4*)(ore + o), vr);
            __stcs((float4*)(oim + o), vi);
        }
    }
}

extern "C" void kernel_launch(void* const* d_in, const int* in_sizes, int n_in,
                              void* d_out, int out_size)
{
    const float* re = (const float*)d_in[0];
    const float* im = (const float*)d_in[1];
    float* out = (float*)d_out;

    const int n_elems = in_sizes[0];        // 8*4096*1024
    const int rows    = n_elems / NFFT;     // 32768

    float* ore = out;
    float* oim = out + (size_t)n_elems;

    ifft1024_v6<<<rows, TPB>>>(re, im, ore, oim);
}

// round 11
// speedup vs baseline: 1.2258x; 1.2258x over previous
#include <cuda_runtime.h>

#define NFFT 1024
#define TPB  128
// float2-word skew: conflict-free for ALL four access patterns used below
#define SK(a) ((a) + ((a) >> 4))

#define CMUL(r, i, cr, ci) { float _t = (r)*(cr) - (i)*(ci); (i) = (r)*(ci) + (i)*(cr); (r) = _t; }

// Inverse 4-pt DFT (twiddle sign +i), outputs in natural order.
__device__ __forceinline__ void idft4(
    float ar, float ai, float br, float bi,
    float cr, float ci, float dr, float di,
    float& o0r, float& o0i, float& o1r, float& o1i,
    float& o2r, float& o2i, float& o3r, float& o3i)
{
    float t0r = ar + cr, t0i = ai + ci;
    float t1r = ar - cr, t1i = ai - ci;
    float t2r = br + dr, t2i = bi + di;
    float t3r = br - dr, t3i = bi - di;
    o0r = t0r + t2r;  o0i = t0i + t2i;
    o2r = t0r - t2r;  o2i = t0i - t2i;
    o1r = t1r - t3i;  o1i = t1i + t3r;   // + i*t3
    o3r = t1r + t3i;  o3i = t1i - t3r;   // - i*t3
}

// Inverse 16-pt DFT (sign +i), natural-order in/out, via 4x4 decomposition.
__device__ __forceinline__ void idft16(const float* xr, const float* xi,
                                       float* Xr, float* Xi)
{
    const float C1 = 0.9238795325112867f;   // cos(pi/8)
    const float S1 = 0.3826834323650898f;   // sin(pi/8)
    const float C2 = 0.7071067811865476f;

    float yr[16], yi[16];
    #pragma unroll
    for (int n0 = 0; n0 < 4; n0++) {
        idft4(xr[n0], xi[n0], xr[n0+4], xi[n0+4],
              xr[n0+8], xi[n0+8], xr[n0+12], xi[n0+12],
              yr[n0], yi[n0], yr[n0+4], yi[n0+4],
              yr[n0+8], yi[n0+8], yr[n0+12], yi[n0+12]);
    }
    CMUL(yr[5],  yi[5],   C1,  S1);
    CMUL(yr[9],  yi[9],   C2,  C2);
    CMUL(yr[13], yi[13],  S1,  C1);
    CMUL(yr[6],  yi[6],   C2,  C2);
    { float t = yr[10]; yr[10] = -yi[10]; yi[10] = t; }
    CMUL(yr[14], yi[14], -C2,  C2);
    CMUL(yr[7],  yi[7],   S1,  C1);
    CMUL(yr[11], yi[11], -C2,  C2);
    CMUL(yr[15], yi[15], -C1, -S1);
    #pragma unroll
    for (int m = 0; m < 4; m++) {
        idft4(yr[4*m+0], yi[4*m+0], yr[4*m+1], yi[4*m+1],
              yr[4*m+2], yi[4*m+2], yr[4*m+3], yi[4*m+3],
              Xr[m],    Xi[m],    Xr[m+4],  Xi[m+4],
              Xr[m+8],  Xi[m+8],  Xr[m+12], Xi[m+12]);
    }
}

__global__ __launch_bounds__(TPB, 10)
void ifft1024_v7(const float* __restrict__ xre,
                 const float* __restrict__ xim,
                 float* __restrict__ ore,
                 float* __restrict__ oim)
{
    __shared__ float2 sm[2][1088];   // 1024 + skew padding, per row

    const int tid = threadIdx.x;
    const int lr  = tid >> 6;        // local row 0/1
    const int t   = tid & 63;        // thread within row
    float2* s = sm[lr];
    const size_t base = ((size_t)blockIdx.x * 2 + lr) * NFFT;
    const float scale = 1.0f / (float)NFFT;
    const float TWO_PI = 6.283185307179586f;

    float xr[16], xi[16], Xr[16], Xi[16];

    // ============ stage 0: radix-16, L=1 (global read, coalesced, streaming) ============
    #pragma unroll
    for (int c = 0; c < 16; c++) {
        xr[c] = __ldcs(xre + base + t + 64 * c) * scale;
        xi[c] = __ldcs(xim + base + t + 64 * c) * scale;
    }
    idft16(xr, xi, Xr, Xi);
    #pragma unroll
    for (int c = 0; c < 16; c++)
        s[SK(16 * t + c)] = make_float2(Xr[c], Xi[c]);
    __syncthreads();

    // ============ stage 1: radix-16, L=16 (in-place: read-all, sync, write) ============
    #pragma unroll
    for (int c = 0; c < 16; c++) {
        float2 v = s[SK(t + 64 * c)];
        xr[c] = v.x;  xi[c] = v.y;
    }
    __syncthreads();
    {   // twiddle: x[c] *= W256^{b*c}, b = t mod 16
        const int b = t & 15;
        float wr, wi;
        __sincosf(TWO_PI * (float)b * (1.0f / 256.0f), &wi, &wr);
        float cwr = wr, cwi = wi;
        #pragma unroll
        for (int c = 1; c < 16; c++) {
            CMUL(xr[c], xi[c], cwr, cwi);
            if (c < 15) { float nr = cwr*wr - cwi*wi; cwi = cwr*wi + cwi*wr; cwr = nr; }
        }
    }
    idft16(xr, xi, Xr, Xi);
    {
        const int wb = (t & 15) + ((t >> 4) << 8);   // b + 256*(t/16)
        #pragma unroll
        for (int c = 0; c < 16; c++)
            s[SK(wb + 16 * c)] = make_float2(Xr[c], Xi[c]);
    }
    __syncthreads();

    // ============ stage 2: radix-4, L=256, j = 4t+d, natural-order global store ============
    {
        float outR[4][4], outI[4][4];   // [k][d]
        float wr, wi;
        __sincosf(TWO_PI * (float)(4 * t) * (1.0f / 1024.0f), &wi, &wr);
        const float dc = 0.9999811752826011f;    // cos(2*pi/1024)
        const float ds = 0.006135884649154475f;  // sin(2*pi/1024)

        #pragma unroll
        for (int d = 0; d < 4; d++) {
            const int j = 4 * t + d;
            float ar[4], ai[4];
            #pragma unroll
            for (int k = 0; k < 4; k++) {
                float2 v = s[SK(j + 256 * k)];
                ar[k] = v.x;  ai[k] = v.y;
            }
            float w2r = wr*wr - wi*wi, w2i = 2.0f*wr*wi;
            float w3r = w2r*wr - w2i*wi, w3i = w2r*wi + w2i*wr;
            CMUL(ar[1], ai[1], wr,  wi);
            CMUL(ar[2], ai[2], w2r, w2i);
            CMUL(ar[3], ai[3], w3r, w3i);
            idft4(ar[0], ai[0], ar[1], ai[1], ar[2], ai[2], ar[3], ai[3],
                  outR[0][d], outI[0][d], outR[1][d], outI[1][d],
                  outR[2][d], outI[2][d], outR[3][d], outI[3][d]);
            if (d < 3) { float nr = wr*dc - wi*ds; wi = wr*ds + wi*dc; wr = nr; }
        }
        #pragma unroll
        for (int k = 0; k < 4; k++) {
            const size_t o = base + (size_t)(4 * t + 256 * k);
            float4 vr = make_float4(outR[k][0], outR[k][1], outR[k][2], outR[k][3]);
            float4 vi = make_float4(outI[k][0], outI[k][1], outI[k][2], outI[k][3]);
            __stcs((float4*)(ore + o), vr);
            __stcs((float4*)(oim + o), vi);
        }
    }
}

extern "C" void kernel_launch(void* const* d_in, const int* in_sizes, int n_in,
                              void* d_out, int out_size)
{
    const float* re = (const float*)d_in[0];
    const float* im = (const float*)d_in[1];
    float* out = (float*)d_out;

    const int n_elems = in_sizes[0];        // 8*4096*1024
    const int rows    = n_elems / NFFT;     // 32768

    float* ore = out;
    float* oim = out + (size_t)n_elems;

    ifft1024_v7<<<rows / 2, TPB>>>(re, im, ore, oim);
}